// round 9
// baseline (speedup 1.0000x reference)
#include <cuda_runtime.h>
#include <cuda_fp16.h>
#include <cstdint>
#include <math.h>

#define BATCH 4
#define CCH   512
#define NSP   4096
#define GROUPS 32
#define GSIZE  65536

static const long CN  = (long)CCH * NSP;
static const long NNL = (long)NSP * NSP;

// Scratch (device globals — allocation-free per harness rules)
__device__ __half g_ht[BATCH * CCH * NSP];  // normalized h transposed [B][N][C]
__device__ __half g_q [BATCH * CCH * NSP];  // q_t [B][N][C]
__device__ __half g_k [BATCH * CCH * NSP];  // k_t [B][N][C]
__device__ __half g_v [BATCH * CCH * NSP];  // v   [B][C][N]
__device__ __half g_o [BATCH * CCH * NSP];  // O_t [B][N][C]
__device__ __half g_p [BATCH * NSP * NSP];  // attn probs (half)   [B][i][j]
__device__ float  g_s [BATCH * NSP * NSP];  // scores (fp32)       [B][i][j]
__device__ __half g_w [4 * CCH * CCH];      // half wq,wk,wv,wp
__device__ float  g_mu [BATCH * GROUPS];
__device__ float  g_rsd[BATCH * GROUPS];

// ===========================================================================
// helpers
// ===========================================================================
__device__ __forceinline__ uint32_t s2u(const void* p) {
    uint32_t a;
    asm("{ .reg .u64 t; cvta.to.shared.u64 t, %1; cvt.u32.u64 %0, t; }"
        : "=r"(a) : "l"(p));
    return a;
}
__device__ __forceinline__ void cpa16(uint32_t d, const void* s) {
    asm volatile("cp.async.cg.shared.global [%0], [%1], 16;" :: "r"(d), "l"(s));
}
__device__ __forceinline__ void mma16(float* d, const uint32_t* a, const uint32_t* b) {
    asm volatile(
        "mma.sync.aligned.m16n8k16.row.col.f32.f16.f16.f32 "
        "{%0,%1,%2,%3}, {%4,%5,%6,%7}, {%8,%9}, {%0,%1,%2,%3};"
        : "+f"(d[0]), "+f"(d[1]), "+f"(d[2]), "+f"(d[3])
        : "r"(a[0]), "r"(a[1]), "r"(a[2]), "r"(a[3]), "r"(b[0]), "r"(b[1]));
}
__device__ __forceinline__ void ldm4(uint32_t* r, uint32_t addr) {
    asm volatile(
        "ldmatrix.sync.aligned.m8n8.x4.shared.b16 {%0,%1,%2,%3}, [%4];"
        : "=r"(r[0]), "=r"(r[1]), "=r"(r[2]), "=r"(r[3]) : "r"(addr));
}

// ===========================================================================
// GroupNorm stats: one block per (b, group); writes mu/rstd only.
// ===========================================================================
__global__ void gn_stats(const float* __restrict__ x,
                         float* __restrict__ mu_out,
                         float* __restrict__ rsd_out)
{
    const int bg  = blockIdx.x;
    const long base = (long)bg * GSIZE;
    const int tid = threadIdx.x;

    float s = 0.f, ss = 0.f;
    for (int i = tid * 4; i < GSIZE; i += 256 * 4) {
        float4 v = *(const float4*)(x + base + i);
        s  += v.x + v.y + v.z + v.w;
        ss += v.x*v.x + v.y*v.y + v.z*v.z + v.w*v.w;
    }
    __shared__ float rs[256], rq[256];
    rs[tid] = s; rq[tid] = ss;
    __syncthreads();
    for (int o = 128; o > 0; o >>= 1) {
        if (tid < o) { rs[tid] += rs[tid + o]; rq[tid] += rq[tid + o]; }
        __syncthreads();
    }
    if (tid == 0) {
        float mu  = rs[0] * (1.f / GSIZE);
        float var = rq[0] * (1.f / GSIZE) - mu * mu;
        mu_out[bg]  = mu;
        rsd_out[bg] = rsqrtf(var + 1e-6f);
    }
}

// ===========================================================================
// Fused normalize + transpose + fp16 convert: x[C,N] -> h_t[N,C] (half)
// ===========================================================================
__global__ void ntrans_kernel(const float* __restrict__ x,
                              const float* __restrict__ gamma,
                              const float* __restrict__ beta,
                              const float* __restrict__ mu,
                              const float* __restrict__ rsd,
                              __half* __restrict__ out)
{
    __shared__ float t[32][33];
    const int bz = blockIdx.z;
    const float* I = x + (long)bz * CN;
    __half* O = out + (long)bz * CN;
    const int c0 = blockIdx.y * 32, n0 = blockIdx.x * 32;
    const int tx = threadIdx.x, ty = threadIdx.y;   // (32, 8)
#pragma unroll
    for (int i = 0; i < 32; i += 8) {
        const int c = c0 + ty + i;
        const int bg = bz * GROUPS + (c >> 4);      // 16 channels per group
        const float ga = gamma[c] * rsd[bg];
        const float be = beta[c] - mu[bg] * ga;
        t[ty + i][tx] = I[(long)c * NSP + n0 + tx] * ga + be;
    }
    __syncthreads();
#pragma unroll
    for (int i = 0; i < 32; i += 8)
        O[(long)(n0 + ty + i) * CCH + c0 + tx] = __float2half_rn(t[tx][ty + i]);
}

// ===========================================================================
// fp32 -> fp16 convert (weights)
// ===========================================================================
__global__ void tohalf_kernel(const float* __restrict__ in,
                              __half* __restrict__ out, int n)
{
    int i = (blockIdx.x * 256 + threadIdx.x) * 4;
    if (i < n) {
        float4 v = *(const float4*)(in + i);
        __half2 h0 = __floats2half2_rn(v.x, v.y);
        __half2 h1 = __floats2half2_rn(v.z, v.w);
        *(__half2*)(out + i)     = h0;
        *(__half2*)(out + i + 2) = h1;
    }
}

// ===========================================================================
// fp16 tensor-core GEMM: mma.sync.m16n8k16 + ldmatrix + 4-stage cp.async.
//   D[m,n] = alpha * sum_k A[m*lda+k] * B[n*ldb+k] (+biasM[m]) (+biasN[n]) (+R)
// CTA tile 128x128, K-tile 16 (one k16 mma), 4 warps (2x2), warp tile 64x64.
// smem row stride 24 halves (48B): 8 rows tile all 32 banks -> conflict-free
// ldmatrix; 16B alignment holds. 4 stages, issue-ahead 2, 1 barrier/K-tile.
// Dynamic smem: 4 stages * (128+128) rows * 48B = 49152 B.
// ===========================================================================
#define TG_STAGE   12288u              // (A:6144 + B:6144) per stage
#define TG_B_OFF   6144u
#define TG_SMEM_BYTES 49152

template<bool HALF_C>
__global__ void __launch_bounds__(128, 2)
hgemm(const __half* __restrict__ A, const __half* __restrict__ B,
      void* __restrict__ Cv, int lda, int ldb, int ldc,
      long sA, long sB, long sC, long sR,
      int K, float alpha,
      const float* __restrict__ biasM, const float* __restrict__ biasN,
      const float* __restrict__ res)
{
    extern __shared__ __half sm[];
    const uint32_t sbase = s2u(sm);

    const int tid  = threadIdx.x;
    const int lane = tid & 31, wid = tid >> 5;
    const int m0 = blockIdx.y * 128, n0 = blockIdx.x * 128, bz = blockIdx.z;

    const __half* Ab = A + bz * sA + (long)m0 * lda;
    const __half* Bb = B + bz * sB + (long)n0 * ldb;

    // cp.async staging: thread covers rows r0, r0+64; 16B chunk (tid&1)
    const int r0 = tid >> 1;            // 0..63
    const int h8 = (tid & 1) * 8;       // half-element offset (16B)
    const uint32_t stDst = (uint32_t)(r0 * 48 + h8 * 2);
    const __half* pA = Ab + (long)r0 * lda + h8;
    const __half* pB = Bb + (long)r0 * ldb + h8;
    const long aS = (long)64 * lda;
    const long bS = (long)64 * ldb;

    // warp/fragment addressing: warp grid 2x2, warp tile 64x64
    const int qid = lane >> 2, rid = lane & 3;
    const int mw = (wid >> 1) * 64, nw = (wid & 1) * 64;
    const int lr = lane & 7;
    // A: matrix m=lane>>3 -> row = lr + (m&1)*8, chunk = (m>>1)*16B
    const uint32_t aLD = sbase
        + (uint32_t)(mw + lr + ((lane >> 3) & 1) * 8) * 48u
        + (uint32_t)((lane >> 4) & 1) * 16u;
    // B: matrix m -> n' = lr + (m>>1)*8, chunk = (m&1)*16B
    const uint32_t bLD = sbase + TG_B_OFF
        + (uint32_t)(nw + lr + ((lane >> 4) & 1) * 8) * 48u
        + (uint32_t)((lane >> 3) & 1) * 16u;

    float d[4][8][4];
#pragma unroll
    for (int i = 0; i < 4; i++)
#pragma unroll
        for (int j = 0; j < 8; j++)
#pragma unroll
            for (int l = 0; l < 4; l++) d[i][j][l] = 0.f;

    const int NK = K >> 4;

    // prologue: stages 0,1
#pragma unroll
    for (int p = 0; p < 2; p++) {
        const uint32_t ao = sbase + (uint32_t)p * TG_STAGE + stDst;
        const __half* qa = pA + p * 16;
        const __half* qb = pB + p * 16;
        cpa16(ao,                    qa);
        cpa16(ao + 3072u,            qa + aS);     // +64 rows * 48B
        cpa16(ao + TG_B_OFF,         qb);
        cpa16(ao + TG_B_OFF + 3072u, qb + bS);
        asm volatile("cp.async.commit_group;" ::: "memory");
    }

#pragma unroll 1
    for (int kt = 0; kt < NK; kt++) {
        const uint32_t bufo = (uint32_t)(kt & 3) * TG_STAGE;

        asm volatile("cp.async.wait_group 1;" ::: "memory");
        __syncthreads();

        // fragments: 4 B-ldm.x4 (pairs of n-blocks) + 4 A-ldm.x4
        uint32_t bf[4][4], af[4][4];
#pragma unroll
        for (int nj = 0; nj < 4; nj++)
            ldm4(bf[nj], bLD + bufo + (uint32_t)nj * 768u);
#pragma unroll
        for (int mi = 0; mi < 4; mi++)
            ldm4(af[mi], aLD + bufo + (uint32_t)mi * 768u);

        // issue loads for kt+2
        if (kt + 2 < NK) {
            const uint32_t ao = sbase + (uint32_t)((kt + 2) & 3) * TG_STAGE + stDst;
            const __half* qa = pA + (kt + 2) * 16;
            const __half* qb = pB + (kt + 2) * 16;
            cpa16(ao,                    qa);
            cpa16(ao + 3072u,            qa + aS);
            cpa16(ao + TG_B_OFF,         qb);
            cpa16(ao + TG_B_OFF + 3072u, qb + bS);
        }
        asm volatile("cp.async.commit_group;" ::: "memory");

#pragma unroll
        for (int mi = 0; mi < 4; mi++)
#pragma unroll
            for (int ni = 0; ni < 8; ni++)
                mma16(d[mi][ni], af[mi], &bf[ni >> 1][(ni & 1) * 2]);
        // no trailing barrier: 4 stages + issue-ahead 2 + top barrier => safe
    }

    // epilogue
    const float* Rb = res ? (res + bz * sR) : nullptr;
#pragma unroll
    for (int mi = 0; mi < 4; mi++) {
        const int rA = m0 + mw + mi * 16 + qid;
        const int rB = rA + 8;
        const float bmA = biasM ? biasM[rA] : 0.f;
        const float bmB = biasM ? biasM[rB] : 0.f;
#pragma unroll
        for (int ni = 0; ni < 8; ni++) {
            const int col = n0 + nw + ni * 8 + rid * 2;
            float bn0 = 0.f, bn1 = 0.f;
            if (biasN) { bn0 = biasN[col]; bn1 = biasN[col + 1]; }
            float2 v0, v1;
            v0.x = d[mi][ni][0] * alpha + bmA + bn0;
            v0.y = d[mi][ni][1] * alpha + bmA + bn1;
            v1.x = d[mi][ni][2] * alpha + bmB + bn0;
            v1.y = d[mi][ni][3] * alpha + bmB + bn1;
            const long o0 = (long)rA * ldc + col;
            const long o1 = (long)rB * ldc + col;
            if (HALF_C) {
                __half* Ch = (__half*)Cv + bz * sC;
                *(__half2*)(Ch + o0) = __floats2half2_rn(v0.x, v0.y);
                *(__half2*)(Ch + o1) = __floats2half2_rn(v1.x, v1.y);
            } else {
                float* Cf = (float*)Cv + bz * sC;
                if (Rb) {
                    float2 ra = *(const float2*)(Rb + o0);
                    float2 rb = *(const float2*)(Rb + o1);
                    v0.x += ra.x; v0.y += ra.y;
                    v1.x += rb.x; v1.y += rb.y;
                }
                *(float2*)(Cf + o0) = v0;
                *(float2*)(Cf + o1) = v1;
            }
        }
    }
}

// ===========================================================================
// Row softmax over 4096 fp32 scores -> half probs (separate buffer).
// ===========================================================================
__global__ void softmax_kernel(const float* __restrict__ s,
                               __half* __restrict__ pOut)
{
    const long row = blockIdx.x;
    const float* p = s + row * (long)NSP;
    __half* q = pOut + row * (long)NSP;
    const int tid = threadIdx.x;

    __shared__ float buf[NSP];
    __shared__ float red[256];

    float m = -1e30f;
    for (int i = tid * 4; i < NSP; i += 1024) {
        float4 v = *(const float4*)(p + i);
        *(float4*)(buf + i) = v;
        m = fmaxf(m, fmaxf(fmaxf(v.x, v.y), fmaxf(v.z, v.w)));
    }
    red[tid] = m;
    __syncthreads();
    for (int o = 128; o > 0; o >>= 1) {
        if (tid < o) red[tid] = fmaxf(red[tid], red[tid + o]);
        __syncthreads();
    }
    m = red[0];
    __syncthreads();

    float sum = 0.f;
    for (int i = tid * 4; i < NSP; i += 1024) {
        float4 v = *(const float4*)(buf + i);
        v.x = __expf(v.x - m);
        v.y = __expf(v.y - m);
        v.z = __expf(v.z - m);
        v.w = __expf(v.w - m);
        *(float4*)(buf + i) = v;
        sum += v.x + v.y + v.z + v.w;
    }
    red[tid] = sum;
    __syncthreads();
    for (int o = 128; o > 0; o >>= 1) {
        if (tid < o) red[tid] += red[tid + o];
        __syncthreads();
    }
    const float inv = 1.f / red[0];

    for (int i = tid * 4; i < NSP; i += 1024) {
        float4 v = *(const float4*)(buf + i);
        *(__half2*)(q + i)     = __floats2half2_rn(v.x * inv, v.y * inv);
        *(__half2*)(q + i + 2) = __floats2half2_rn(v.z * inv, v.w * inv);
    }
}

// ===========================================================================
extern "C" void kernel_launch(void* const* d_in, const int* in_sizes, int n_in,
                              void* d_out, int out_size)
{
    const float* x     = (const float*)d_in[0];
    const float* gamma = (const float*)d_in[1];
    const float* beta  = (const float*)d_in[2];
    const float* wq    = (const float*)d_in[3];
    const float* bq    = (const float*)d_in[4];
    const float* wk    = (const float*)d_in[5];
    const float* bk    = (const float*)d_in[6];
    const float* wv    = (const float*)d_in[7];
    const float* bv    = (const float*)d_in[8];
    const float* wp    = (const float*)d_in[9];
    const float* bp    = (const float*)d_in[10];
    float* out = (float*)d_out;

    __half *pht, *pq, *pk, *pv, *po, *pp, *pw;
    float *ps, *pmu, *prs;
    cudaGetSymbolAddress((void**)&pht, g_ht);
    cudaGetSymbolAddress((void**)&pq,  g_q);
    cudaGetSymbolAddress((void**)&pk,  g_k);
    cudaGetSymbolAddress((void**)&pv,  g_v);
    cudaGetSymbolAddress((void**)&po,  g_o);
    cudaGetSymbolAddress((void**)&pp,  g_p);
    cudaGetSymbolAddress((void**)&ps,  g_s);
    cudaGetSymbolAddress((void**)&pw,  g_w);
    cudaGetSymbolAddress((void**)&pmu, g_mu);
    cudaGetSymbolAddress((void**)&prs, g_rsd);

    cudaFuncSetAttribute(hgemm<true>,  cudaFuncAttributeMaxDynamicSharedMemorySize,
                         TG_SMEM_BYTES);
    cudaFuncSetAttribute(hgemm<false>, cudaFuncAttributeMaxDynamicSharedMemorySize,
                         TG_SMEM_BYTES);

    const int WN = CCH * CCH;           // 262144
    __half* rwq = pw;
    __half* rwk = pw + WN;
    __half* rwv = pw + 2 * WN;
    __half* rwp = pw + 3 * WN;

    // 0) convert the weight matrices to fp16
    tohalf_kernel<<<WN / 1024, 256>>>(wq, rwq, WN);
    tohalf_kernel<<<WN / 1024, 256>>>(wk, rwk, WN);
    tohalf_kernel<<<WN / 1024, 256>>>(wv, rwv, WN);
    tohalf_kernel<<<WN / 1024, 256>>>(wp, rwp, WN);

    // 1) GroupNorm stats
    gn_stats<<<BATCH * GROUPS, 256>>>(x, pmu, prs);

    // 2) fused normalize + transpose -> h_t [N,C] (half)
    dim3 gT(NSP / 32, CCH / 32, BATCH);
    ntrans_kernel<<<gT, dim3(32, 8)>>>(x, gamma, beta, pmu, prs, pht);

    // 3) q_t[i,o] = sum_c h_t[i,c] wq[o,c] + bq[o]   (M=NSP, N=CCH)
    dim3 gNC(CCH / 128, NSP / 128, BATCH);   // (4, 32, 4)
    hgemm<true><<<gNC, 128, TG_SMEM_BYTES>>>(pht, rwq, pq, CCH, CCH, CCH,
                                             CN, 0, CN, 0,
                                             CCH, 1.f, nullptr, bq, nullptr);
    hgemm<true><<<gNC, 128, TG_SMEM_BYTES>>>(pht, rwk, pk, CCH, CCH, CCH,
                                             CN, 0, CN, 0,
                                             CCH, 1.f, nullptr, bk, nullptr);

    // 4) v[c,j] = sum_c' wv[c,c'] h_t[j,c'] + bv[c]  (M=CCH, N=NSP)
    dim3 gCN(NSP / 128, CCH / 128, BATCH);   // (32, 4, 4)
    hgemm<true><<<gCN, 128, TG_SMEM_BYTES>>>(rwv, pht, pv, CCH, CCH, NSP,
                                             0, CN, CN, 0,
                                             CCH, 1.f, bv, nullptr, nullptr);

    // 5) scores S[i,j] = scale * sum_c q_t[i,c] k_t[j,c]  (M=N=NSP, fp32 out)
    const float scale = 0.04419417382415922f;  // 512^-0.5
    dim3 gSS(NSP / 128, NSP / 128, BATCH);   // (32, 32, 4)
    hgemm<false><<<gSS, 128, TG_SMEM_BYTES>>>(pq, pk, ps, CCH, CCH, NSP,
                                              CN, CN, NNL, 0,
                                              CCH, scale, nullptr, nullptr, nullptr);

    // 6) softmax over keys -> half probs
    softmax_kernel<<<BATCH * NSP, 256>>>(ps, pp);

    // 7) O_t[i,c] = sum_j P[i,j] v[c,j]   (M=NSP, N=CCH, K=NSP)
    hgemm<true><<<gNC, 128, TG_SMEM_BYTES>>>(pp, pv, po, NSP, NSP, CCH,
                                             NNL, CN, CN, 0,
                                             NSP, 1.f, nullptr, nullptr, nullptr);

    // 8) out[o,n] = sum_c wp[o,c] O_t[n,c] + bp[o] + x[o,n]  (M=CCH, N=NSP)
    hgemm<false><<<gCN, 128, TG_SMEM_BYTES>>>(rwp, po, out, CCH, CCH, NSP,
                                              0, CN, CN, CN,
                                              CCH, 1.f, bp, nullptr, x);
}

// round 10
// speedup vs baseline: 1.9412x; 1.9412x over previous
#include <cuda_runtime.h>
#include <cuda_fp16.h>
#include <cstdint>
#include <math.h>

#define BATCH 4
#define CCH   512
#define NSP   4096
#define GROUPS 32
#define GSIZE  65536

static const long CN  = (long)CCH * NSP;
static const long NNL = (long)NSP * NSP;

// Scratch (device globals — allocation-free per harness rules)
__device__ __half g_ht[BATCH * CCH * NSP];  // normalized h transposed [B][N][C]
__device__ __half g_q [BATCH * CCH * NSP];  // q_t [B][N][C]
__device__ __half g_k [BATCH * CCH * NSP];  // k_t [B][N][C]
__device__ __half g_v [BATCH * CCH * NSP];  // v   [B][C][N]
__device__ __half g_o [BATCH * CCH * NSP];  // O_t [B][N][C]
__device__ __half g_p [BATCH * NSP * NSP];  // attn probs (half)   [B][i][j]
__device__ float  g_s [BATCH * NSP * NSP];  // scores (fp32)       [B][i][j]
__device__ __half g_w [4 * CCH * CCH];      // half wq,wk,wv,wp
__device__ float  g_mu [BATCH * GROUPS];
__device__ float  g_rsd[BATCH * GROUPS];

// ===========================================================================
// helpers
// ===========================================================================
__device__ __forceinline__ uint32_t s2u(const void* p) {
    uint32_t a;
    asm("{ .reg .u64 t; cvta.to.shared.u64 t, %1; cvt.u32.u64 %0, t; }"
        : "=r"(a) : "l"(p));
    return a;
}
__device__ __forceinline__ void cpa16(uint32_t d, const void* s) {
    asm volatile("cp.async.cg.shared.global [%0], [%1], 16;" :: "r"(d), "l"(s));
}
__device__ __forceinline__ void mma16(float* d, const uint32_t* a, const uint32_t* b) {
    asm volatile(
        "mma.sync.aligned.m16n8k16.row.col.f32.f16.f16.f32 "
        "{%0,%1,%2,%3}, {%4,%5,%6,%7}, {%8,%9}, {%0,%1,%2,%3};"
        : "+f"(d[0]), "+f"(d[1]), "+f"(d[2]), "+f"(d[3])
        : "r"(a[0]), "r"(a[1]), "r"(a[2]), "r"(a[3]), "r"(b[0]), "r"(b[1]));
}
__device__ __forceinline__ void ldm4(uint32_t* r, uint32_t addr) {
    asm volatile(
        "ldmatrix.sync.aligned.m8n8.x4.shared.b16 {%0,%1,%2,%3}, [%4];"
        : "=r"(r[0]), "=r"(r[1]), "=r"(r[2]), "=r"(r[3]) : "r"(addr));
}

// ===========================================================================
// GroupNorm stats: one block per (b, group); writes mu/rstd only.
// ===========================================================================
__global__ void gn_stats(const float* __restrict__ x,
                         float* __restrict__ mu_out,
                         float* __restrict__ rsd_out)
{
    const int bg  = blockIdx.x;
    const long base = (long)bg * GSIZE;
    const int tid = threadIdx.x;

    float s = 0.f, ss = 0.f;
    for (int i = tid * 4; i < GSIZE; i += 256 * 4) {
        float4 v = *(const float4*)(x + base + i);
        s  += v.x + v.y + v.z + v.w;
        ss += v.x*v.x + v.y*v.y + v.z*v.z + v.w*v.w;
    }
    __shared__ float rs[256], rq[256];
    rs[tid] = s; rq[tid] = ss;
    __syncthreads();
    for (int o = 128; o > 0; o >>= 1) {
        if (tid < o) { rs[tid] += rs[tid + o]; rq[tid] += rq[tid + o]; }
        __syncthreads();
    }
    if (tid == 0) {
        float mu  = rs[0] * (1.f / GSIZE);
        float var = rq[0] * (1.f / GSIZE) - mu * mu;
        mu_out[bg]  = mu;
        rsd_out[bg] = rsqrtf(var + 1e-6f);
    }
}

// ===========================================================================
// Fused normalize + transpose + fp16 convert: x[C,N] -> h_t[N,C] (half)
// ===========================================================================
__global__ void ntrans_kernel(const float* __restrict__ x,
                              const float* __restrict__ gamma,
                              const float* __restrict__ beta,
                              const float* __restrict__ mu,
                              const float* __restrict__ rsd,
                              __half* __restrict__ out)
{
    __shared__ float t[32][33];
    const int bz = blockIdx.z;
    const float* I = x + (long)bz * CN;
    __half* O = out + (long)bz * CN;
    const int c0 = blockIdx.y * 32, n0 = blockIdx.x * 32;
    const int tx = threadIdx.x, ty = threadIdx.y;   // (32, 8)
#pragma unroll
    for (int i = 0; i < 32; i += 8) {
        const int c = c0 + ty + i;
        const int bg = bz * GROUPS + (c >> 4);      // 16 channels per group
        const float ga = gamma[c] * rsd[bg];
        const float be = beta[c] - mu[bg] * ga;
        t[ty + i][tx] = I[(long)c * NSP + n0 + tx] * ga + be;
    }
    __syncthreads();
#pragma unroll
    for (int i = 0; i < 32; i += 8)
        O[(long)(n0 + ty + i) * CCH + c0 + tx] = __float2half_rn(t[tx][ty + i]);
}

// ===========================================================================
// fp32 -> fp16 convert (weights)
// ===========================================================================
__global__ void tohalf_kernel(const float* __restrict__ in,
                              __half* __restrict__ out, int n)
{
    int i = (blockIdx.x * 256 + threadIdx.x) * 4;
    if (i < n) {
        float4 v = *(const float4*)(in + i);
        *(__half2*)(out + i)     = __floats2half2_rn(v.x, v.y);
        *(__half2*)(out + i + 2) = __floats2half2_rn(v.z, v.w);
    }
}

// ===========================================================================
// fp16 tensor-core GEMM: mma.sync.m16n8k16 + ldmatrix + 4-stage cp.async.
//   D[m,n] = alpha * sum_k A[m*lda+k] * B[n*ldb+k] (+biasM[m]) (+biasN[n]) (+R)
// CTA tile 128x128, K-tile 32 halves (2 k16 steps), 4 warps (2x2),
// warp tile 64x64. smem row = 32 halves data in 40-half (80B) stride:
// 8 rows tile all 32 banks -> conflict-free ldmatrix; 16B aligned.
// Per warp-ktile: 16 ldm.x4 + 64 mma (same mix as the tf32 winner, half NK).
// 4 stages, issue-ahead 2, 1 barrier/K-tile.
// Dynamic smem: 4 stages * (128+128) rows * 80B = 81920 B.
// ===========================================================================
#define TG_STAGE   20480u              // (A:10240 + B:10240) per stage
#define TG_B_OFF   10240u
#define TG_SMEM_BYTES 81920

template<bool HALF_C>
__global__ void __launch_bounds__(128, 2)
hgemm(const __half* __restrict__ A, const __half* __restrict__ B,
      void* __restrict__ Cv, int lda, int ldb, int ldc,
      long sA, long sB, long sC, long sR,
      int K, float alpha,
      const float* __restrict__ biasM, const float* __restrict__ biasN,
      const float* __restrict__ res)
{
    extern __shared__ __half sm[];
    const uint32_t sbase = s2u(sm);

    const int tid  = threadIdx.x;
    const int lane = tid & 31, wid = tid >> 5;
    const int m0 = blockIdx.y * 128, n0 = blockIdx.x * 128, bz = blockIdx.z;

    const __half* Ab = A + bz * sA + (long)m0 * lda;
    const __half* Bb = B + bz * sB + (long)n0 * ldb;

    // cp.async staging: rows r0+{0,32,64,96}, 16B chunk c8
    const int r0 = tid >> 2;            // 0..31
    const int c8 = (tid & 3) * 8;       // half-element offset (16B chunks)
    const uint32_t stDst = (uint32_t)(r0 * 80 + (tid & 3) * 16);
    const __half* pA = Ab + (long)r0 * lda + c8;
    const __half* pB = Bb + (long)r0 * ldb + c8;
    const long aS = (long)32 * lda;
    const long bS = (long)32 * ldb;

    // warp/fragment addressing: warp grid 2x2, warp tile 64x64
    const int qid = lane >> 2, rid = lane & 3;
    const int mw = (wid >> 1) * 64, nw = (wid & 1) * 64;
    // A x4 per (mi,ks): rows mw+mi*16+(lane&15), k-halves ks*16 + (lane>>4)*8
    const uint32_t aLD = sbase + (uint32_t)(mw + (lane & 15)) * 80u
                       + (uint32_t)((lane >> 4) & 1) * 16u;
    // B x4 per (nj,ks): n rows nw+nj*16+(lane&7)+((lane>>4)&1)*8,
    //                   k-halves ks*16 + ((lane>>3)&1)*8
    const uint32_t bLD = sbase + TG_B_OFF
        + (uint32_t)(nw + (lane & 7) + ((lane >> 4) & 1) * 8) * 80u
        + (uint32_t)((lane >> 3) & 1) * 16u;

    float d[4][8][4];
#pragma unroll
    for (int i = 0; i < 4; i++)
#pragma unroll
        for (int j = 0; j < 8; j++)
#pragma unroll
            for (int l = 0; l < 4; l++) d[i][j][l] = 0.f;

    const int NK = K >> 5;              // K-tile = 32 halves

    // prologue: stages 0,1
#pragma unroll
    for (int p = 0; p < 2; p++) {
        const uint32_t ao = sbase + (uint32_t)p * TG_STAGE + stDst;
        const __half* qa = pA + p * 32;
        const __half* qb = pB + p * 32;
#pragma unroll
        for (int i = 0; i < 4; i++) {
            cpa16(ao + (uint32_t)i * 2560u,            qa + i * aS);
            cpa16(ao + TG_B_OFF + (uint32_t)i * 2560u, qb + i * bS);
        }
        asm volatile("cp.async.commit_group;" ::: "memory");
    }

#pragma unroll 1
    for (int kt = 0; kt < NK; kt++) {
        const uint32_t bufo = (uint32_t)(kt & 3) * TG_STAGE;

        asm volatile("cp.async.wait_group 1;" ::: "memory");
        __syncthreads();

        // all fragments: 8 B-ldm.x4 + 8 A-ldm.x4 (2 k-steps)
        uint32_t bf[2][4][4], af[2][4][4];
#pragma unroll
        for (int ks = 0; ks < 2; ks++) {
#pragma unroll
            for (int nj = 0; nj < 4; nj++)
                ldm4(bf[ks][nj], bLD + bufo + (uint32_t)nj * 1280u
                                      + (uint32_t)ks * 32u);
#pragma unroll
            for (int mi = 0; mi < 4; mi++)
                ldm4(af[ks][mi], aLD + bufo + (uint32_t)mi * 1280u
                                      + (uint32_t)ks * 32u);
        }

        // issue loads for kt+2
        if (kt + 2 < NK) {
            const uint32_t ao = sbase + (uint32_t)((kt + 2) & 3) * TG_STAGE + stDst;
            const __half* qa = pA + (kt + 2) * 32;
            const __half* qb = pB + (kt + 2) * 32;
#pragma unroll
            for (int i = 0; i < 4; i++) {
                cpa16(ao + (uint32_t)i * 2560u,            qa + i * aS);
                cpa16(ao + TG_B_OFF + (uint32_t)i * 2560u, qb + i * bS);
            }
        }
        asm volatile("cp.async.commit_group;" ::: "memory");

#pragma unroll
        for (int ks = 0; ks < 2; ks++)
#pragma unroll
            for (int mi = 0; mi < 4; mi++)
#pragma unroll
                for (int ni = 0; ni < 8; ni++)
                    mma16(d[mi][ni], af[ks][mi],
                          &bf[ks][ni >> 1][(ni & 1) * 2]);
        // no trailing barrier: 4 stages + issue-ahead 2 + top barrier => safe
    }

    // epilogue
    const float* Rb = res ? (res + bz * sR) : nullptr;
#pragma unroll
    for (int mi = 0; mi < 4; mi++) {
        const int rA = m0 + mw + mi * 16 + qid;
        const int rB = rA + 8;
        const float bmA = biasM ? biasM[rA] : 0.f;
        const float bmB = biasM ? biasM[rB] : 0.f;
#pragma unroll
        for (int ni = 0; ni < 8; ni++) {
            const int col = n0 + nw + ni * 8 + rid * 2;
            float bn0 = 0.f, bn1 = 0.f;
            if (biasN) { bn0 = biasN[col]; bn1 = biasN[col + 1]; }
            float2 v0, v1;
            v0.x = d[mi][ni][0] * alpha + bmA + bn0;
            v0.y = d[mi][ni][1] * alpha + bmA + bn1;
            v1.x = d[mi][ni][2] * alpha + bmB + bn0;
            v1.y = d[mi][ni][3] * alpha + bmB + bn1;
            const long o0 = (long)rA * ldc + col;
            const long o1 = (long)rB * ldc + col;
            if (HALF_C) {
                __half* Ch = (__half*)Cv + bz * sC;
                *(__half2*)(Ch + o0) = __floats2half2_rn(v0.x, v0.y);
                *(__half2*)(Ch + o1) = __floats2half2_rn(v1.x, v1.y);
            } else {
                float* Cf = (float*)Cv + bz * sC;
                if (Rb) {
                    float2 ra = *(const float2*)(Rb + o0);
                    float2 rb = *(const float2*)(Rb + o1);
                    v0.x += ra.x; v0.y += ra.y;
                    v1.x += rb.x; v1.y += rb.y;
                }
                *(float2*)(Cf + o0) = v0;
                *(float2*)(Cf + o1) = v1;
            }
        }
    }
}

// ===========================================================================
// Row softmax over 4096 fp32 scores -> half probs (separate buffer).
// ===========================================================================
__global__ void softmax_kernel(const float* __restrict__ s,
                               __half* __restrict__ pOut)
{
    const long row = blockIdx.x;
    const float* p = s + row * (long)NSP;
    __half* q = pOut + row * (long)NSP;
    const int tid = threadIdx.x;

    __shared__ float buf[NSP];
    __shared__ float red[256];

    float m = -1e30f;
    for (int i = tid * 4; i < NSP; i += 1024) {
        float4 v = *(const float4*)(p + i);
        *(float4*)(buf + i) = v;
        m = fmaxf(m, fmaxf(fmaxf(v.x, v.y), fmaxf(v.z, v.w)));
    }
    red[tid] = m;
    __syncthreads();
    for (int o = 128; o > 0; o >>= 1) {
        if (tid < o) red[tid] = fmaxf(red[tid], red[tid + o]);
        __syncthreads();
    }
    m = red[0];
    __syncthreads();

    float sum = 0.f;
    for (int i = tid * 4; i < NSP; i += 1024) {
        float4 v = *(const float4*)(buf + i);
        v.x = __expf(v.x - m);
        v.y = __expf(v.y - m);
        v.z = __expf(v.z - m);
        v.w = __expf(v.w - m);
        *(float4*)(buf + i) = v;
        sum += v.x + v.y + v.z + v.w;
    }
    red[tid] = sum;
    __syncthreads();
    for (int o = 128; o > 0; o >>= 1) {
        if (tid < o) red[tid] += red[tid + o];
        __syncthreads();
    }
    const float inv = 1.f / red[0];

    for (int i = tid * 4; i < NSP; i += 1024) {
        float4 v = *(const float4*)(buf + i);
        *(__half2*)(q + i)     = __floats2half2_rn(v.x * inv, v.y * inv);
        *(__half2*)(q + i + 2) = __floats2half2_rn(v.z * inv, v.w * inv);
    }
}

// ===========================================================================
extern "C" void kernel_launch(void* const* d_in, const int* in_sizes, int n_in,
                              void* d_out, int out_size)
{
    const float* x     = (const float*)d_in[0];
    const float* gamma = (const float*)d_in[1];
    const float* beta  = (const float*)d_in[2];
    const float* wq    = (const float*)d_in[3];
    const float* bq    = (const float*)d_in[4];
    const float* wk    = (const float*)d_in[5];
    const float* bk    = (const float*)d_in[6];
    const float* wv    = (const float*)d_in[7];
    const float* bv    = (const float*)d_in[8];
    const float* wp    = (const float*)d_in[9];
    const float* bp    = (const float*)d_in[10];
    float* out = (float*)d_out;

    __half *pht, *pq, *pk, *pv, *po, *pp, *pw;
    float *ps, *pmu, *prs;
    cudaGetSymbolAddress((void**)&pht, g_ht);
    cudaGetSymbolAddress((void**)&pq,  g_q);
    cudaGetSymbolAddress((void**)&pk,  g_k);
    cudaGetSymbolAddress((void**)&pv,  g_v);
    cudaGetSymbolAddress((void**)&po,  g_o);
    cudaGetSymbolAddress((void**)&pp,  g_p);
    cudaGetSymbolAddress((void**)&ps,  g_s);
    cudaGetSymbolAddress((void**)&pw,  g_w);
    cudaGetSymbolAddress((void**)&pmu, g_mu);
    cudaGetSymbolAddress((void**)&prs, g_rsd);

    cudaFuncSetAttribute(hgemm<true>,  cudaFuncAttributeMaxDynamicSharedMemorySize,
                         TG_SMEM_BYTES);
    cudaFuncSetAttribute(hgemm<false>, cudaFuncAttributeMaxDynamicSharedMemorySize,
                         TG_SMEM_BYTES);

    const int WN = CCH * CCH;           // 262144
    __half* rwq = pw;
    __half* rwk = pw + WN;
    __half* rwv = pw + 2 * WN;
    __half* rwp = pw + 3 * WN;

    // 0) convert the weight matrices to fp16
    tohalf_kernel<<<WN / 1024, 256>>>(wq, rwq, WN);
    tohalf_kernel<<<WN / 1024, 256>>>(wk, rwk, WN);
    tohalf_kernel<<<WN / 1024, 256>>>(wv, rwv, WN);
    tohalf_kernel<<<WN / 1024, 256>>>(wp, rwp, WN);

    // 1) GroupNorm stats
    gn_stats<<<BATCH * GROUPS, 256>>>(x, pmu, prs);

    // 2) fused normalize + transpose -> h_t [N,C] (half)
    dim3 gT(NSP / 32, CCH / 32, BATCH);
    ntrans_kernel<<<gT, dim3(32, 8)>>>(x, gamma, beta, pmu, prs, pht);

    // 3) q_t[i,o] = sum_c h_t[i,c] wq[o,c] + bq[o]   (M=NSP, N=CCH)
    dim3 gNC(CCH / 128, NSP / 128, BATCH);   // (4, 32, 4)
    hgemm<true><<<gNC, 128, TG_SMEM_BYTES>>>(pht, rwq, pq, CCH, CCH, CCH,
                                             CN, 0, CN, 0,
                                             CCH, 1.f, nullptr, bq, nullptr);
    hgemm<true><<<gNC, 128, TG_SMEM_BYTES>>>(pht, rwk, pk, CCH, CCH, CCH,
                                             CN, 0, CN, 0,
                                             CCH, 1.f, nullptr, bk, nullptr);

    // 4) v[c,j] = sum_c' wv[c,c'] h_t[j,c'] + bv[c]  (M=CCH, N=NSP)
    dim3 gCN(NSP / 128, CCH / 128, BATCH);   // (32, 4, 4)
    hgemm<true><<<gCN, 128, TG_SMEM_BYTES>>>(rwv, pht, pv, CCH, CCH, NSP,
                                             0, CN, CN, 0,
                                             CCH, 1.f, bv, nullptr, nullptr);

    // 5) scores S[i,j] = scale * sum_c q_t[i,c] k_t[j,c]  (M=N=NSP, fp32 out)
    const float scale = 0.04419417382415922f;  // 512^-0.5
    dim3 gSS(NSP / 128, NSP / 128, BATCH);   // (32, 32, 4)
    hgemm<false><<<gSS, 128, TG_SMEM_BYTES>>>(pq, pk, ps, CCH, CCH, NSP,
                                              CN, CN, NNL, 0,
                                              CCH, scale, nullptr, nullptr, nullptr);

    // 6) softmax over keys -> half probs
    softmax_kernel<<<BATCH * NSP, 256>>>(ps, pp);

    // 7) O_t[i,c] = sum_j P[i,j] v[c,j]   (M=NSP, N=CCH, K=NSP)
    hgemm<true><<<gNC, 128, TG_SMEM_BYTES>>>(pp, pv, po, NSP, NSP, CCH,
                                             NNL, CN, CN, 0,
                                             NSP, 1.f, nullptr, nullptr, nullptr);

    // 8) out[o,n] = sum_c wp[o,c] O_t[n,c] + bp[o] + x[o,n]  (M=CCH, N=NSP)
    hgemm<false><<<gCN, 128, TG_SMEM_BYTES>>>(rwp, po, out, CCH, CCH, NSP,
                                              0, CN, CN, CN,
                                              CCH, 1.f, bp, nullptr, x);
}

// round 11
// speedup vs baseline: 2.1269x; 1.0957x over previous
#include <cuda_runtime.h>
#include <cuda_fp16.h>
#include <cstdint>
#include <math.h>

#define BATCH 4
#define CCH   512
#define NSP   4096
#define GROUPS 32
#define GSIZE  65536

static const long CN  = (long)CCH * NSP;
static const long NNL = (long)NSP * NSP;

// Scratch (device globals — allocation-free per harness rules)
__device__ __half g_ht[BATCH * CCH * NSP];  // normalized h transposed [B][N][C]
__device__ __half g_q [BATCH * CCH * NSP];  // q_t [B][N][C]
__device__ __half g_k [BATCH * CCH * NSP];  // k_t [B][N][C]
__device__ __half g_v [BATCH * CCH * NSP];  // v   [B][C][N]
__device__ __half g_o [BATCH * CCH * NSP];  // O_t [B][N][C]
__device__ __half g_p [BATCH * NSP * NSP];  // scores -> probs (in place, half)
__device__ __half g_w [4 * CCH * CCH];      // half wq,wk,wv,wp
__device__ float  g_mu [BATCH * GROUPS];
__device__ float  g_rsd[BATCH * GROUPS];

// ===========================================================================
// helpers
// ===========================================================================
__device__ __forceinline__ uint32_t s2u(const void* p) {
    uint32_t a;
    asm("{ .reg .u64 t; cvta.to.shared.u64 t, %1; cvt.u32.u64 %0, t; }"
        : "=r"(a) : "l"(p));
    return a;
}
__device__ __forceinline__ void cpa16(uint32_t d, const void* s) {
    asm volatile("cp.async.cg.shared.global [%0], [%1], 16;" :: "r"(d), "l"(s));
}
__device__ __forceinline__ void mma16(float* d, const uint32_t* a, const uint32_t* b) {
    asm volatile(
        "mma.sync.aligned.m16n8k16.row.col.f32.f16.f16.f32 "
        "{%0,%1,%2,%3}, {%4,%5,%6,%7}, {%8,%9}, {%0,%1,%2,%3};"
        : "+f"(d[0]), "+f"(d[1]), "+f"(d[2]), "+f"(d[3])
        : "r"(a[0]), "r"(a[1]), "r"(a[2]), "r"(a[3]), "r"(b[0]), "r"(b[1]));
}
__device__ __forceinline__ void ldm4(uint32_t* r, uint32_t addr) {
    asm volatile(
        "ldmatrix.sync.aligned.m8n8.x4.shared.b16 {%0,%1,%2,%3}, [%4];"
        : "=r"(r[0]), "=r"(r[1]), "=r"(r[2]), "=r"(r[3]) : "r"(addr));
}

// ===========================================================================
// GroupNorm stats: one block per (b, group); writes mu/rstd only.
// ===========================================================================
__global__ void gn_stats(const float* __restrict__ x,
                         float* __restrict__ mu_out,
                         float* __restrict__ rsd_out)
{
    const int bg  = blockIdx.x;
    const long base = (long)bg * GSIZE;
    const int tid = threadIdx.x;

    float s = 0.f, ss = 0.f;
    for (int i = tid * 4; i < GSIZE; i += 256 * 4) {
        float4 v = *(const float4*)(x + base + i);
        s  += v.x + v.y + v.z + v.w;
        ss += v.x*v.x + v.y*v.y + v.z*v.z + v.w*v.w;
    }
    __shared__ float rs[256], rq[256];
    rs[tid] = s; rq[tid] = ss;
    __syncthreads();
    for (int o = 128; o > 0; o >>= 1) {
        if (tid < o) { rs[tid] += rs[tid + o]; rq[tid] += rq[tid + o]; }
        __syncthreads();
    }
    if (tid == 0) {
        float mu  = rs[0] * (1.f / GSIZE);
        float var = rq[0] * (1.f / GSIZE) - mu * mu;
        mu_out[bg]  = mu;
        rsd_out[bg] = rsqrtf(var + 1e-6f);
    }
}

// ===========================================================================
// Fused normalize + transpose + fp16 convert: x[C,N] -> h_t[N,C] (half)
// ===========================================================================
__global__ void ntrans_kernel(const float* __restrict__ x,
                              const float* __restrict__ gamma,
                              const float* __restrict__ beta,
                              const float* __restrict__ mu,
                              const float* __restrict__ rsd,
                              __half* __restrict__ out)
{
    __shared__ float t[32][33];
    const int bz = blockIdx.z;
    const float* I = x + (long)bz * CN;
    __half* O = out + (long)bz * CN;
    const int c0 = blockIdx.y * 32, n0 = blockIdx.x * 32;
    const int tx = threadIdx.x, ty = threadIdx.y;   // (32, 8)
#pragma unroll
    for (int i = 0; i < 32; i += 8) {
        const int c = c0 + ty + i;
        const int bg = bz * GROUPS + (c >> 4);      // 16 channels per group
        const float ga = gamma[c] * rsd[bg];
        const float be = beta[c] - mu[bg] * ga;
        t[ty + i][tx] = I[(long)c * NSP + n0 + tx] * ga + be;
    }
    __syncthreads();
#pragma unroll
    for (int i = 0; i < 32; i += 8)
        O[(long)(n0 + ty + i) * CCH + c0 + tx] = __float2half_rn(t[tx][ty + i]);
}

// ===========================================================================
// fp32 -> fp16 convert: all 4 weight matrices in one launch (blockIdx.y picks)
// ===========================================================================
__global__ void tohalf4_kernel(const float* __restrict__ w0,
                               const float* __restrict__ w1,
                               const float* __restrict__ w2,
                               const float* __restrict__ w3,
                               __half* __restrict__ out, int n)
{
    const float* in = (blockIdx.y == 0) ? w0 : (blockIdx.y == 1) ? w1
                    : (blockIdx.y == 2) ? w2 : w3;
    __half* o = out + (long)blockIdx.y * n;
    int i = (blockIdx.x * 256 + threadIdx.x) * 4;
    if (i < n) {
        float4 v = *(const float4*)(in + i);
        *(__half2*)(o + i)     = __floats2half2_rn(v.x, v.y);
        *(__half2*)(o + i + 2) = __floats2half2_rn(v.z, v.w);
    }
}

// ===========================================================================
// fp16 tensor-core GEMM: mma.sync.m16n8k16 + ldmatrix + 4-stage cp.async.
//   D[m,n] = alpha * sum_k A[m*lda+k] * B[n*ldb+k] (+biasM[m]) (+biasN[n]) (+R)
// CTA tile 128x128, K-tile 32 halves (2 k16 steps), 4 warps (2x2),
// warp tile 64x64. smem row = 32 halves data in 40-half (80B) stride.
// 4 stages, issue-ahead 2, 1 barrier/K-tile. Dyn smem 81920 B, 2 CTAs/SM.
// ===========================================================================
#define TG_STAGE   20480u              // (A:10240 + B:10240) per stage
#define TG_B_OFF   10240u
#define TG_SMEM_BYTES 81920

template<bool HALF_C>
__global__ void __launch_bounds__(128, 2)
hgemm(const __half* __restrict__ A, const __half* __restrict__ B,
      void* __restrict__ Cv, int lda, int ldb, int ldc,
      long sA, long sB, long sC, long sR,
      int K, float alpha,
      const float* __restrict__ biasM, const float* __restrict__ biasN,
      const float* __restrict__ res)
{
    extern __shared__ __half sm[];
    const uint32_t sbase = s2u(sm);

    const int tid  = threadIdx.x;
    const int lane = tid & 31, wid = tid >> 5;
    const int m0 = blockIdx.y * 128, n0 = blockIdx.x * 128, bz = blockIdx.z;

    const __half* Ab = A + bz * sA + (long)m0 * lda;
    const __half* Bb = B + bz * sB + (long)n0 * ldb;

    // cp.async staging: rows r0+{0,32,64,96}, 16B chunk c8
    const int r0 = tid >> 2;            // 0..31
    const int c8 = (tid & 3) * 8;       // half-element offset (16B chunks)
    const uint32_t stDst = (uint32_t)(r0 * 80 + (tid & 3) * 16);
    const __half* pA = Ab + (long)r0 * lda + c8;
    const __half* pB = Bb + (long)r0 * ldb + c8;
    const long aS = (long)32 * lda;
    const long bS = (long)32 * ldb;

    // warp/fragment addressing: warp grid 2x2, warp tile 64x64
    const int qid = lane >> 2, rid = lane & 3;
    const int mw = (wid >> 1) * 64, nw = (wid & 1) * 64;
    const uint32_t aLD = sbase + (uint32_t)(mw + (lane & 15)) * 80u
                       + (uint32_t)((lane >> 4) & 1) * 16u;
    const uint32_t bLD = sbase + TG_B_OFF
        + (uint32_t)(nw + (lane & 7) + ((lane >> 4) & 1) * 8) * 80u
        + (uint32_t)((lane >> 3) & 1) * 16u;

    float d[4][8][4];
#pragma unroll
    for (int i = 0; i < 4; i++)
#pragma unroll
        for (int j = 0; j < 8; j++)
#pragma unroll
            for (int l = 0; l < 4; l++) d[i][j][l] = 0.f;

    const int NK = K >> 5;              // K-tile = 32 halves

    // prologue: stages 0,1
#pragma unroll
    for (int p = 0; p < 2; p++) {
        const uint32_t ao = sbase + (uint32_t)p * TG_STAGE + stDst;
        const __half* qa = pA + p * 32;
        const __half* qb = pB + p * 32;
#pragma unroll
        for (int i = 0; i < 4; i++) {
            cpa16(ao + (uint32_t)i * 2560u,            qa + i * aS);
            cpa16(ao + TG_B_OFF + (uint32_t)i * 2560u, qb + i * bS);
        }
        asm volatile("cp.async.commit_group;" ::: "memory");
    }

#pragma unroll 1
    for (int kt = 0; kt < NK; kt++) {
        const uint32_t bufo = (uint32_t)(kt & 3) * TG_STAGE;

        asm volatile("cp.async.wait_group 1;" ::: "memory");
        __syncthreads();

        // all fragments: 8 B-ldm.x4 + 8 A-ldm.x4 (2 k-steps)
        uint32_t bf[2][4][4], af[2][4][4];
#pragma unroll
        for (int ks = 0; ks < 2; ks++) {
#pragma unroll
            for (int nj = 0; nj < 4; nj++)
                ldm4(bf[ks][nj], bLD + bufo + (uint32_t)nj * 1280u
                                      + (uint32_t)ks * 32u);
#pragma unroll
            for (int mi = 0; mi < 4; mi++)
                ldm4(af[ks][mi], aLD + bufo + (uint32_t)mi * 1280u
                                      + (uint32_t)ks * 32u);
        }

        // issue loads for kt+2
        if (kt + 2 < NK) {
            const uint32_t ao = sbase + (uint32_t)((kt + 2) & 3) * TG_STAGE + stDst;
            const __half* qa = pA + (kt + 2) * 32;
            const __half* qb = pB + (kt + 2) * 32;
#pragma unroll
            for (int i = 0; i < 4; i++) {
                cpa16(ao + (uint32_t)i * 2560u,            qa + i * aS);
                cpa16(ao + TG_B_OFF + (uint32_t)i * 2560u, qb + i * bS);
            }
        }
        asm volatile("cp.async.commit_group;" ::: "memory");

#pragma unroll
        for (int ks = 0; ks < 2; ks++)
#pragma unroll
            for (int mi = 0; mi < 4; mi++)
#pragma unroll
                for (int ni = 0; ni < 8; ni++)
                    mma16(d[mi][ni], af[ks][mi],
                          &bf[ks][ni >> 1][(ni & 1) * 2]);
        // no trailing barrier: 4 stages + issue-ahead 2 + top barrier => safe
    }

    // epilogue
    const float* Rb = res ? (res + bz * sR) : nullptr;
#pragma unroll
    for (int mi = 0; mi < 4; mi++) {
        const int rA = m0 + mw + mi * 16 + qid;
        const int rB = rA + 8;
        const float bmA = biasM ? biasM[rA] : 0.f;
        const float bmB = biasM ? biasM[rB] : 0.f;
#pragma unroll
        for (int ni = 0; ni < 8; ni++) {
            const int col = n0 + nw + ni * 8 + rid * 2;
            float bn0 = 0.f, bn1 = 0.f;
            if (biasN) { bn0 = biasN[col]; bn1 = biasN[col + 1]; }
            float2 v0, v1;
            v0.x = d[mi][ni][0] * alpha + bmA + bn0;
            v0.y = d[mi][ni][1] * alpha + bmA + bn1;
            v1.x = d[mi][ni][2] * alpha + bmB + bn0;
            v1.y = d[mi][ni][3] * alpha + bmB + bn1;
            const long o0 = (long)rA * ldc + col;
            const long o1 = (long)rB * ldc + col;
            if (HALF_C) {
                __half* Ch = (__half*)Cv + bz * sC;
                *(__half2*)(Ch + o0) = __floats2half2_rn(v0.x, v0.y);
                *(__half2*)(Ch + o1) = __floats2half2_rn(v1.x, v1.y);
            } else {
                float* Cf = (float*)Cv + bz * sC;
                if (Rb) {
                    float2 ra = *(const float2*)(Rb + o0);
                    float2 rb = *(const float2*)(Rb + o1);
                    v0.x += ra.x; v0.y += ra.y;
                    v1.x += rb.x; v1.y += rb.y;
                }
                *(float2*)(Cf + o0) = v0;
                *(float2*)(Cf + o1) = v1;
            }
        }
    }
}

// ===========================================================================
// In-place register softmax over 4096 half scores -> half probs.
// 256 threads/row; 16 values per thread held in registers; shuffle reductions.
// ===========================================================================
__global__ void softmax_kernel(__half* __restrict__ s)
{
    const long row = blockIdx.x;
    __half* p = s + row * (long)NSP;
    const int tid = threadIdx.x;
    const int lane = tid & 31, wrp = tid >> 5;

    __shared__ float red[8];

    // load 16 halves (2 x 16B) into fp32 registers
    float v[16];
#pragma unroll
    for (int c = 0; c < 2; c++) {
        int4 pk = *(const int4*)(p + (tid + c * 256) * 8);
        const __half2* h2 = (const __half2*)&pk;
#pragma unroll
        for (int j = 0; j < 4; j++) {
            float2 f = __half22float2(h2[j]);
            v[c * 8 + j * 2]     = f.x;
            v[c * 8 + j * 2 + 1] = f.y;
        }
    }

    // max
    float m = v[0];
#pragma unroll
    for (int k = 1; k < 16; k++) m = fmaxf(m, v[k]);
#pragma unroll
    for (int o = 16; o > 0; o >>= 1)
        m = fmaxf(m, __shfl_xor_sync(0xffffffffu, m, o));
    if (lane == 0) red[wrp] = m;
    __syncthreads();
    m = red[lane & 7];
#pragma unroll
    for (int o = 4; o > 0; o >>= 1)
        m = fmaxf(m, __shfl_xor_sync(0xffffffffu, m, o));

    // exp + sum
    float sum = 0.f;
#pragma unroll
    for (int k = 0; k < 16; k++) {
        v[k] = __expf(v[k] - m);
        sum += v[k];
    }
#pragma unroll
    for (int o = 16; o > 0; o >>= 1)
        sum += __shfl_xor_sync(0xffffffffu, sum, o);
    __syncthreads();
    if (lane == 0) red[wrp] = sum;
    __syncthreads();
    sum = red[lane & 7];
#pragma unroll
    for (int o = 4; o > 0; o >>= 1)
        sum += __shfl_xor_sync(0xffffffffu, sum, o);
    const float inv = 1.f / sum;

    // write back (half)
#pragma unroll
    for (int c = 0; c < 2; c++) {
        int4 pk;
        __half2* h2 = (__half2*)&pk;
#pragma unroll
        for (int j = 0; j < 4; j++)
            h2[j] = __floats2half2_rn(v[c * 8 + j * 2] * inv,
                                      v[c * 8 + j * 2 + 1] * inv);
        *(int4*)(p + (tid + c * 256) * 8) = pk;
    }
}

// ===========================================================================
extern "C" void kernel_launch(void* const* d_in, const int* in_sizes, int n_in,
                              void* d_out, int out_size)
{
    const float* x     = (const float*)d_in[0];
    const float* gamma = (const float*)d_in[1];
    const float* beta  = (const float*)d_in[2];
    const float* wq    = (const float*)d_in[3];
    const float* bq    = (const float*)d_in[4];
    const float* wk    = (const float*)d_in[5];
    const float* bk    = (const float*)d_in[6];
    const float* wv    = (const float*)d_in[7];
    const float* bv    = (const float*)d_in[8];
    const float* wp    = (const float*)d_in[9];
    const float* bp    = (const float*)d_in[10];
    float* out = (float*)d_out;

    __half *pht, *pq, *pk, *pv, *po, *pp, *pw;
    float *pmu, *prs;
    cudaGetSymbolAddress((void**)&pht, g_ht);
    cudaGetSymbolAddress((void**)&pq,  g_q);
    cudaGetSymbolAddress((void**)&pk,  g_k);
    cudaGetSymbolAddress((void**)&pv,  g_v);
    cudaGetSymbolAddress((void**)&po,  g_o);
    cudaGetSymbolAddress((void**)&pp,  g_p);
    cudaGetSymbolAddress((void**)&pw,  g_w);
    cudaGetSymbolAddress((void**)&pmu, g_mu);
    cudaGetSymbolAddress((void**)&prs, g_rsd);

    cudaFuncSetAttribute(hgemm<true>,  cudaFuncAttributeMaxDynamicSharedMemorySize,
                         TG_SMEM_BYTES);
    cudaFuncSetAttribute(hgemm<false>, cudaFuncAttributeMaxDynamicSharedMemorySize,
                         TG_SMEM_BYTES);

    const int WN = CCH * CCH;           // 262144
    __half* rwq = pw;
    __half* rwk = pw + WN;
    __half* rwv = pw + 2 * WN;
    __half* rwp = pw + 3 * WN;

    // 0) convert the 4 weight matrices to fp16 (one launch)
    tohalf4_kernel<<<dim3(WN / 1024, 4), 256>>>(wq, wk, wv, wp, pw, WN);

    // 1) GroupNorm stats
    gn_stats<<<BATCH * GROUPS, 256>>>(x, pmu, prs);

    // 2) fused normalize + transpose -> h_t [N,C] (half)
    dim3 gT(NSP / 32, CCH / 32, BATCH);
    ntrans_kernel<<<gT, dim3(32, 8)>>>(x, gamma, beta, pmu, prs, pht);

    // 3) q_t[i,o] = sum_c h_t[i,c] wq[o,c] + bq[o]   (M=NSP, N=CCH)
    dim3 gNC(CCH / 128, NSP / 128, BATCH);   // (4, 32, 4)
    hgemm<true><<<gNC, 128, TG_SMEM_BYTES>>>(pht, rwq, pq, CCH, CCH, CCH,
                                             CN, 0, CN, 0,
                                             CCH, 1.f, nullptr, bq, nullptr);
    hgemm<true><<<gNC, 128, TG_SMEM_BYTES>>>(pht, rwk, pk, CCH, CCH, CCH,
                                             CN, 0, CN, 0,
                                             CCH, 1.f, nullptr, bk, nullptr);

    // 4) v[c,j] = sum_c' wv[c,c'] h_t[j,c'] + bv[c]  (M=CCH, N=NSP)
    dim3 gCN(NSP / 128, CCH / 128, BATCH);   // (32, 4, 4)
    hgemm<true><<<gCN, 128, TG_SMEM_BYTES>>>(rwv, pht, pv, CCH, CCH, NSP,
                                             0, CN, CN, 0,
                                             CCH, 1.f, bv, nullptr, nullptr);

    // 5) scores S[i,j] = scale * sum_c q_t[i,c] k_t[j,c] -> half, into g_p
    const float scale = 0.04419417382415922f;  // 512^-0.5
    dim3 gSS(NSP / 128, NSP / 128, BATCH);   // (32, 32, 4)
    hgemm<true><<<gSS, 128, TG_SMEM_BYTES>>>(pq, pk, pp, CCH, CCH, NSP,
                                             CN, CN, NNL, 0,
                                             CCH, scale, nullptr, nullptr, nullptr);

    // 6) in-place softmax over keys (half -> half)
    softmax_kernel<<<BATCH * NSP, 256>>>(pp);

    // 7) O_t[i,c] = sum_j P[i,j] v[c,j]   (M=NSP, N=CCH, K=NSP)
    hgemm<true><<<gNC, 128, TG_SMEM_BYTES>>>(pp, pv, po, NSP, NSP, CCH,
                                             NNL, CN, CN, 0,
                                             NSP, 1.f, nullptr, nullptr, nullptr);

    // 8) out[o,n] = sum_c wp[o,c] O_t[n,c] + bp[o] + x[o,n]  (M=CCH, N=NSP)
    hgemm<false><<<gCN, 128, TG_SMEM_BYTES>>>(rwp, po, out, CCH, CCH, NSP,
                                              0, CN, CN, CN,
                                              CCH, 1.f, bp, nullptr, x);
}